// round 16
// baseline (speedup 1.0000x reference)
#include <cuda_runtime.h>
#include <cuda_bf16.h>
#include <cstdint>

// Problem constants
#define NB 4
#define SLEN 32768
#define C1 128
#define C2C 256
#define C3 512
#define L1O 16384
#define L2O 8192
#define L3O 4096
#define VOCAB 2048
#define KCB 4
#define NCODES (KCB * VOCAB)   // 8192
#define MTOT (NB * L3O)        // 16384
#define NGRP 1024              // 8-code subgroups per row (8192/8)
#define GRP_CB 256             // subgroups per codebook per row

typedef unsigned long long u64;

// bf16 split activations, transposed: X [b][pos][CI], 4 guard rows each side.
__device__ ulonglong2 g_X1h[NB * (L1O + 8) * C1 / 8];
__device__ ulonglong2 g_X1l[NB * (L1O + 8) * C1 / 8];
__device__ ulonglong2 g_X2h[NB * (L2O + 8) * C2C / 8];
__device__ ulonglong2 g_X2l[NB * (L2O + 8) * C2C / 8];
// split weights [7][CO][CI]
__device__ ulonglong2 g_W2h[7 * C2C * C1 / 8];
__device__ ulonglong2 g_W2l[7 * C2C * C1 / 8];
__device__ ulonglong2 g_W3h[7 * C3 * C2C / 8];
__device__ ulonglong2 g_W3l[7 * C3 * C2C / 8];
// vq operands
__device__ ulonglong2 g_Ah[MTOT * 512 / 8];      // feats hi  [m][k] (conv3 output)
__device__ ulonglong2 g_Al[MTOT * 512 / 8];
__device__ ulonglong2 g_Bh[NCODES * 512 / 8];    // codes hi  [n][k]
__device__ ulonglong2 g_Bl[NCODES * 512 / 8];
__device__ float  g_c2[NCODES];
__device__ float  g_thr[MTOT];                   // per-row threshold 2*eb + 0.25
__device__ uint32_t g_gkey32[(size_t)MTOT * NGRP]; // per group: encdist24|mask8
__device__ uint32_t g_items[(size_t)MTOT * NGRP];  // per-cb partitions
__device__ uint32_t g_misc[8];                   // [1]=maxBh2 [2]=maxBl2 [4+cb]=count
__device__ u64    g_res[MTOT * KCB];             // final per (row, cb) key

// ---------------------------------------------------------------------------
// helpers
// ---------------------------------------------------------------------------
__device__ __forceinline__ void cp16(uint32_t dst, const void* src) {
    asm volatile("cp.async.cg.shared.global [%0], [%1], 16;" :: "r"(dst), "l"(src));
}
__device__ __forceinline__ void cp_commit() { asm volatile("cp.async.commit_group;"); }
__device__ __forceinline__ void cp_wait0()  { asm volatile("cp.async.wait_group 0;"); }

__device__ __forceinline__ uint32_t smem_u32(const void* p) {
    return (uint32_t)__cvta_generic_to_shared(p);
}

__device__ __forceinline__ u64 dist_key(float v, int n) {
    unsigned int fb = __float_as_uint(v);
    fb = (fb & 0x80000000u) ? ~fb : (fb | 0x80000000u);
    return ((u64)fb << 32) | (unsigned int)n;
}
__device__ __forceinline__ float dec_bits(unsigned int x) {
    unsigned int vb = (x & 0x80000000u) ? (x & 0x7fffffffu) : ~x;
    return __uint_as_float(vb);
}
__device__ __forceinline__ unsigned int enc_bits(float v) {
    unsigned int tb = __float_as_uint(v);
    return (tb & 0x80000000u) ? ~tb : (tb | 0x80000000u);
}

__device__ __forceinline__ void ldm4(uint32_t* r, uint32_t addr) {
    asm volatile("ldmatrix.sync.aligned.m8n8.x4.shared.b16 {%0,%1,%2,%3}, [%4];"
                 : "=r"(r[0]), "=r"(r[1]), "=r"(r[2]), "=r"(r[3]) : "r"(addr));
}
__device__ __forceinline__ void mma16816(float* c, const uint32_t* a,
                                         uint32_t b0, uint32_t b1) {
    asm volatile(
        "mma.sync.aligned.m16n8k16.row.col.f32.bf16.bf16.f32 "
        "{%0,%1,%2,%3}, {%4,%5,%6,%7}, {%8,%9}, {%0,%1,%2,%3};"
        : "+f"(c[0]), "+f"(c[1]), "+f"(c[2]), "+f"(c[3])
        : "r"(a[0]), "r"(a[1]), "r"(a[2]), "r"(a[3]), "r"(b0), "r"(b1));
}

// smem swizzle (rows of 64 B = 4 x 16B chunks)
__device__ __forceinline__ int swz(int row, int c) {
    return row * 64 + ((c ^ ((row & 3) ^ ((row >> 2) & 1))) << 4);
}
// conv smem swizzle for 32 B rows (2 chunks)
__device__ __forceinline__ int s3(int row) {
    return (row ^ (row >> 1) ^ (row >> 2)) & 1;
}
// unpack 8 bf16 (uint4) -> 8 floats (exact: bf16 = fp32 top bits)
__device__ __forceinline__ void bf8(const uint4 v, float* o) {
    o[0] = __uint_as_float(v.x << 16); o[1] = __uint_as_float(v.x & 0xffff0000u);
    o[2] = __uint_as_float(v.y << 16); o[3] = __uint_as_float(v.y & 0xffff0000u);
    o[4] = __uint_as_float(v.z << 16); o[5] = __uint_as_float(v.z & 0xffff0000u);
    o[6] = __uint_as_float(v.w << 16); o[7] = __uint_as_float(v.w & 0xffff0000u);
}

// ---------------------------------------------------------------------------
// prep: res init + guard zeroing + misc counters
// ---------------------------------------------------------------------------
__global__ void prep_kernel(u64* res, uint32_t* misc,
                            uint32_t* x1h, uint32_t* x1l,
                            uint32_t* x2h, uint32_t* x2l) {
    int i = blockIdx.x * 256 + threadIdx.x;
    if (i < MTOT * KCB) res[i] = ~0ull;
    if (i < 8) misc[i] = 0u;
    if (i < 4096) {
        int half = i >> 11, j = i & 2047;
        int b = j >> 9, r = (j >> 6) & 7, w = j & 63;
        int row = (r < 4) ? r : (L1O + r);
        uint32_t* p = half ? x1l : x1h;
        p[(size_t)(b * (L1O + 8) + row) * 64 + w] = 0u;
    } else if (i < 4096 + 8192) {
        int j = i - 4096;
        int half = j >> 12; j &= 4095;
        int b = j >> 10, r = (j >> 7) & 7, w = j & 127;
        int row = (r < 4) ? r : (L2O + r);
        uint32_t* p = half ? x2l : x2h;
        p[(size_t)(b * (L2O + 8) + row) * 128 + w] = 0u;
    }
}

// ---------------------------------------------------------------------------
// split weights: w [CO][CI][7] fp32 -> Wh/Wl [7][CO][CI] bf16
// ---------------------------------------------------------------------------
__global__ void split_W(const float* __restrict__ w,
                        __nv_bfloat16* __restrict__ wh,
                        __nv_bfloat16* __restrict__ wl, int CO, int CI) {
    int i = blockIdx.x * 256 + threadIdx.x;
    if (i >= CO * CI * 7) return;
    int co = i / (CI * 7);
    int r  = i % (CI * 7);
    int ci = r / 7, t = r % 7;
    float v = w[i];
    __nv_bfloat16 h = __float2bfloat16(v);
    wh[((size_t)t * CO + co) * CI + ci] = h;
    wl[((size_t)t * CO + co) * CI + ci] = __float2bfloat16(v - __bfloat162float(h));
}

// ---------------------------------------------------------------------------
// conv1: [B,1,32768] -> relu -> X1 [b][pos][128] bf16 hi/lo (offset 4 rows)
// ---------------------------------------------------------------------------
__global__ void conv1_kernel(const float* __restrict__ x,
                             const float* __restrict__ w,
                             const float* __restrict__ bias,
                             __nv_bfloat16* __restrict__ yh,
                             __nv_bfloat16* __restrict__ yl) {
    int tid = threadIdx.x;
    int co = tid & 127;
    int l  = blockIdx.x * 2 + (tid >> 7);
    int b  = blockIdx.z;
    const float* xb = x + b * SLEN;
    float acc = bias[co];
#pragma unroll
    for (int t = 0; t < 7; ++t) {
        int g = 2 * l + t - 3;
        float xv = (g >= 0 && g < SLEN) ? xb[g] : 0.0f;
        acc = fmaf(w[co * 7 + t], xv, acc);
    }
    acc = fmaxf(acc, 0.0f);
    __nv_bfloat16 h = __float2bfloat16(acc);
    size_t o = (size_t)(b * (L1O + 8) + l + 4) * C1 + co;
    yh[o] = h;
    yl[o] = __float2bfloat16(acc - __bfloat162float(h));
}

// ---------------------------------------------------------------------------
// conv via mma.sync bf16 split (hh + hl + lh). Single buffer, 2 CTAs/SM.
// ---------------------------------------------------------------------------
#define SLAB_PAR  4352
#define SLAB_HALF 8704
#define SLAB_SZ   17408
#define W_HALF    28672
#define CBUF      74752

template <int CI>
__global__ __launch_bounds__(256, 2) void conv_mma(
        const __nv_bfloat16* __restrict__ Xh, const __nv_bfloat16* __restrict__ Xl,
        const __nv_bfloat16* __restrict__ Wh, const __nv_bfloat16* __restrict__ Wl,
        const float* __restrict__ bias,
        __nv_bfloat16* __restrict__ Yh, __nv_bfloat16* __restrict__ Yl,
        int L_in, int L_out, int CO, int do_relu, int y_pad, int y_off) {
    extern __shared__ __align__(16) char dsm[];
    const uint32_t bb = smem_u32(dsm);

    const int tid  = threadIdx.x;
    const int lane = tid & 31;
    const int wid  = tid >> 5;
    const int wm   = wid >> 1;
    const int wn   = wid & 1;
    const int l0  = blockIdx.x * 128;
    const int co0 = blockIdx.y * 128;
    const int b   = blockIdx.z;

    float acc[2][8][4];
#pragma unroll
    for (int i = 0; i < 2; ++i)
#pragma unroll
        for (int j = 0; j < 8; ++j)
#pragma unroll
            for (int q = 0; q < 4; ++q) acc[i][j][q] = 0.0f;

    auto load_chunk = [&](int ch) {
        const int ci0 = ch * 16;
        for (int i = tid; i < 262 * 4; i += 256) {
            int rel = i >> 2;
            int half = (i >> 1) & 1, ck = i & 1;
            int e = rel >> 1, par = rel & 1;
            const __nv_bfloat16* src = (half ? Xl : Xh) +
                (size_t)(b * (L_in + 8) + 2 * l0 + rel) * CI + ci0 + ck * 8;
            cp16(bb + half * SLAB_HALF + par * SLAB_PAR + e * 32 +
                 ((ck ^ s3(e)) << 4), src);
        }
#pragma unroll
        for (int r = 0; r < 14; ++r) {
            int i = tid + r * 256;
            int row = i >> 2;
            int half = (i >> 1) & 1, ck = i & 1;
            int t = row >> 7, col = row & 127;
            const __nv_bfloat16* src = (half ? Wl : Wh) +
                (size_t)(t * CO + co0 + col) * CI + ci0 + ck * 8;
            cp16(bb + SLAB_SZ + half * W_HALF + row * 32 +
                 ((ck ^ s3(row)) << 4), src);
        }
    };

    const int a_r = lane & 15;
    const int a_h = lane >> 4;
    const int b_r = (lane & 7) + ((lane >> 4) << 3);
    const int b_h = (lane >> 3) & 1;

    const int NCH = CI / 16;
    for (int ch = 0; ch < NCH; ++ch) {
        load_chunk(ch);
        cp_commit();
        cp_wait0();
        __syncthreads();
#pragma unroll
        for (int t = 0; t < 7; ++t) {
            const int par = (t + 1) & 1;
            const int shift = (t + 1) >> 1;
            uint32_t aH[2][4], aL[2][4];
#pragma unroll
            for (int mt = 0; mt < 2; ++mt) {
                int e = wm * 32 + mt * 16 + a_r + shift;
                uint32_t sa = bb + par * SLAB_PAR + e * 32 + ((a_h ^ s3(e)) << 4);
                ldm4(aH[mt], sa);
                ldm4(aL[mt], sa + SLAB_HALF);
            }
#pragma unroll
            for (int g = 0; g < 4; ++g) {
                uint32_t bH[4], bL[4];
                int row = t * 128 + wn * 64 + g * 16 + b_r;
                uint32_t sb = bb + SLAB_SZ + row * 32 + ((b_h ^ s3(row)) << 4);
                ldm4(bH, sb);
                ldm4(bL, sb + W_HALF);
#pragma unroll
                for (int mt = 0; mt < 2; ++mt) {
                    mma16816(acc[mt][g * 2],     aH[mt], bH[0], bH[1]);
                    mma16816(acc[mt][g * 2 + 1], aH[mt], bH[2], bH[3]);
                    mma16816(acc[mt][g * 2],     aH[mt], bL[0], bL[1]);
                    mma16816(acc[mt][g * 2 + 1], aH[mt], bL[2], bL[3]);
                    mma16816(acc[mt][g * 2],     aL[mt], bH[0], bH[1]);
                    mma16816(acc[mt][g * 2 + 1], aL[mt], bH[2], bH[3]);
                }
            }
        }
        if (ch + 1 < NCH) __syncthreads();
    }

    const size_t ybase = (size_t)b * (L_out + y_pad) + y_off;
#pragma unroll
    for (int mt = 0; mt < 2; ++mt)
#pragma unroll
        for (int j = 0; j < 8; ++j)
#pragma unroll
            for (int h8 = 0; h8 < 2; ++h8) {
                int l = l0 + wm * 32 + mt * 16 + (lane >> 2) + h8 * 8;
                int co = co0 + wn * 64 + j * 8 + (lane & 3) * 2;
                float v0 = acc[mt][j][h8 * 2]     + __ldg(&bias[co]);
                float v1 = acc[mt][j][h8 * 2 + 1] + __ldg(&bias[co + 1]);
                if (do_relu) { v0 = fmaxf(v0, 0.0f); v1 = fmaxf(v1, 0.0f); }
                __nv_bfloat16 h0 = __float2bfloat16(v0);
                __nv_bfloat16 h1 = __float2bfloat16(v1);
                __nv_bfloat162 hp; hp.x = h0; hp.y = h1;
                __nv_bfloat162 lp;
                lp.x = __float2bfloat16(v0 - __bfloat162float(h0));
                lp.y = __float2bfloat16(v1 - __bfloat162float(h1));
                size_t o = (ybase + l) * CO + co;
                *(__nv_bfloat162*)(Yh + o) = hp;
                *(__nv_bfloat162*)(Yl + o) = lp;
            }
}

// ---------------------------------------------------------------------------
// fused split_B + bnorm: one pass over cb -> Bh/Bl + c2 + max split norms
// ---------------------------------------------------------------------------
__global__ void splitb_kernel(const float* __restrict__ cb,
                              __nv_bfloat16* __restrict__ bh,
                              __nv_bfloat16* __restrict__ bl,
                              float* __restrict__ c2,
                              uint32_t* __restrict__ misc) {
    int code = blockIdx.x * 8 + (threadIdx.x >> 5);
    int lane = threadIdx.x & 31;
    if (code >= NCODES) return;
    const float* row = cb + (size_t)code * 512 + lane * 16;
    float s = 0.0f, h2 = 0.0f, l2 = 0.0f;
    unsigned int hw[8], lw[8];
#pragma unroll
    for (int q = 0; q < 4; ++q) {
        float4 v = *(const float4*)(row + q * 4);
        float vv[4] = {v.x, v.y, v.z, v.w};
#pragma unroll
        for (int e = 0; e < 2; ++e) {
            float a0 = vv[e * 2], a1 = vv[e * 2 + 1];
            __nv_bfloat16 hb0 = __float2bfloat16(a0);
            __nv_bfloat16 hb1 = __float2bfloat16(a1);
            float hf0 = __bfloat162float(hb0), hf1 = __bfloat162float(hb1);
            float lf0 = a0 - hf0, lf1 = a1 - hf1;
            __nv_bfloat16 lb0 = __float2bfloat16(lf0);
            __nv_bfloat16 lb1 = __float2bfloat16(lf1);
            float lq0 = __bfloat162float(lb0), lq1 = __bfloat162float(lb1);
            __nv_bfloat162 hp; hp.x = hb0; hp.y = hb1;
            __nv_bfloat162 lp; lp.x = lb0; lp.y = lb1;
            hw[q * 2 + e] = *(unsigned int*)&hp;
            lw[q * 2 + e] = *(unsigned int*)&lp;
            s  = fmaf(a0, a0, fmaf(a1, a1, s));
            h2 = fmaf(hf0, hf0, fmaf(hf1, hf1, h2));
            l2 = fmaf(lq0, lq0, fmaf(lq1, lq1, l2));
        }
    }
    uint4* dh = (uint4*)(bh + (size_t)code * 512 + lane * 16);
    uint4* dl = (uint4*)(bl + (size_t)code * 512 + lane * 16);
    dh[0] = make_uint4(hw[0], hw[1], hw[2], hw[3]);
    dh[1] = make_uint4(hw[4], hw[5], hw[6], hw[7]);
    dl[0] = make_uint4(lw[0], lw[1], lw[2], lw[3]);
    dl[1] = make_uint4(lw[4], lw[5], lw[6], lw[7]);
#pragma unroll
    for (int o = 16; o > 0; o >>= 1) {
        s  += __shfl_down_sync(0xffffffffu, s, o);
        h2 += __shfl_down_sync(0xffffffffu, h2, o);
        l2 += __shfl_down_sync(0xffffffffu, l2, o);
    }
    if (lane == 0) {
        c2[code] = s;
        atomicMax(&misc[1], __float_as_uint(h2));
        atomicMax(&misc[2], __float_as_uint(l2));
    }
}

// ---------------------------------------------------------------------------
// thr: per feats row, threshold 2*eb + 0.25 from split norms
// ---------------------------------------------------------------------------
__global__ void thr_kernel(const __nv_bfloat16* __restrict__ Ah,
                           const __nv_bfloat16* __restrict__ Al,
                           const uint32_t* __restrict__ misc,
                           float* __restrict__ thr) {
    int row = blockIdx.x * 8 + (threadIdx.x >> 5);
    int lane = threadIdx.x & 31;
    if (row >= MTOT) return;
    const uint4* ph = (const uint4*)(Ah + (size_t)row * 512 + lane * 16);
    const uint4* pl = (const uint4*)(Al + (size_t)row * 512 + lane * 16);
    float fh[16], fl[16];
    bf8(ph[0], fh); bf8(ph[1], fh + 8);
    bf8(pl[0], fl); bf8(pl[1], fl + 8);
    float sh = 0.0f, sl = 0.0f;
#pragma unroll
    for (int e = 0; e < 16; ++e) {
        sh = fmaf(fh[e], fh[e], sh);
        sl = fmaf(fl[e], fl[e], sl);
    }
#pragma unroll
    for (int o = 16; o > 0; o >>= 1) {
        sh += __shfl_down_sync(0xffffffffu, sh, o);
        sl += __shfl_down_sync(0xffffffffu, sl, o);
    }
    if (lane == 0) {
        float maxBh2 = __uint_as_float(misc[1]);
        float maxBl2 = __uint_as_float(misc[2]);
        float eb = 2.0f * (sqrtf(sh * maxBl2) + sqrtf(sl * maxBh2)
                           + sqrtf(sl * maxBl2));
        thr[row] = 2.0f * eb + 0.25f;
    }
}

// ---------------------------------------------------------------------------
// Fused per-codebook approx VQ + inline flag.
// Block = (128-row m-tile, one codebook). A tile resident in smem (128 KB);
// B streamed per 128-code n-subtile in 32-k chunks (double-buffered).
// Epilogue per subtile writes group keys (gkey); final phase re-reads them
// (L2-hot) and emits refine work items. Grid: (MTOT/128) per launch.
// ---------------------------------------------------------------------------
#define VA_SZ 131072
#define VB_SZ 8192
#define VSMEM (VA_SZ + 2 * VB_SZ)

__global__ __launch_bounds__(256, 1) void vq_fused(
        const __nv_bfloat16* __restrict__ Ah, const __nv_bfloat16* __restrict__ Bh,
        const float* __restrict__ c2, const float* __restrict__ thr,
        uint32_t* __restrict__ gkey, uint32_t* __restrict__ misc,
        uint32_t* __restrict__ items, int cbk) {
    extern __shared__ __align__(16) char dsm[];
    __shared__ uint32_t sG[128][16];

    const int tid  = threadIdx.x;
    const int lane = tid & 31;
    const int wid  = tid >> 5;
    const int wm   = wid >> 1;           // 0..3: m block of 32
    const int wn   = wid & 1;            // 0..1: n block of 64
    const int m0 = blockIdx.x * 128;
    const int nbase = cbk * VOCAB;
    const uint32_t sA = smem_u32(dsm);
    const uint32_t sB = sA + VA_SZ;

    // A tile: 16 k-chunks x (128 rows x 32 k) swizzled; 32 cp16/thread
#pragma unroll
    for (int r = 0; r < 32; ++r) {
        int i = tid + r * 256;           // 0..8191
        int kc = i >> 9;
        int row = (i >> 2) & 127;
        int cc = i & 3;
        cp16(sA + kc * 8192 + swz(row, cc),
             Ah + (size_t)(m0 + row) * 512 + kc * 32 + cc * 8);
    }
    auto load_B = [&](int it, int buf) {
        int ns = it >> 4, kc = it & 15;
#pragma unroll
        for (int r = 0; r < 2; ++r) {
            int i = tid + r * 256;       // 0..511
            int row = i >> 2, cc = i & 3;
            cp16(sB + buf * VB_SZ + swz(row, cc),
                 Bh + (size_t)(nbase + ns * 128 + row) * 512 + kc * 32 + cc * 8);
        }
    };
    load_B(0, 0);
    cp_commit();

    const int a_r = lane & 15;
    const int a_h = lane >> 4;
    const int b_r = (lane & 7) + ((lane >> 4) << 3);
    const int b_h = (lane >> 3) & 1;

    for (int ns = 0; ns < 16; ++ns) {
        float acc[2][8][4];
#pragma unroll
        for (int i = 0; i < 2; ++i)
#pragma unroll
            for (int j = 0; j < 8; ++j)
#pragma unroll
                for (int q = 0; q < 4; ++q) acc[i][j][q] = 0.0f;

        for (int kc = 0; kc < 16; ++kc) {
            const int it = ns * 16 + kc;
            const int buf = it & 1;
            cp_wait0();
            __syncthreads();
            if (it + 1 < 256) { load_B(it + 1, (it + 1) & 1); cp_commit(); }

            const uint32_t aC = sA + kc * 8192;
            const uint32_t bC = sB + buf * VB_SZ;
#pragma unroll
            for (int s = 0; s < 2; ++s) {
                uint32_t a[2][4];
#pragma unroll
                for (int mt = 0; mt < 2; ++mt) {
                    int r = wm * 32 + mt * 16 + a_r;
                    ldm4(a[mt], aC + swz(r, s * 2 + a_h));
                }
#pragma unroll
                for (int g = 0; g < 4; ++g) {
                    uint32_t bF[4];
                    int r = wn * 64 + g * 16 + b_r;
                    ldm4(bF, bC + swz(r, s * 2 + b_h));
#pragma unroll
                    for (int mt = 0; mt < 2; ++mt) {
                        mma16816(acc[mt][g * 2],     a[mt], bF[0], bF[1]);
                        mma16816(acc[mt][g * 2 + 1], a[mt], bF[2], bF[3]);
                    }
                }
            }
        }

        // epilogue(ns): group keys + masks -> sG -> gkey
        const int n0 = nbase + ns * 128;
        float c2v[16];
#pragma unroll
        for (int j = 0; j < 8; ++j)
#pragma unroll
            for (int cb = 0; cb < 2; ++cb)
                c2v[j * 2 + cb] =
                    __ldg(&c2[n0 + wn * 64 + j * 8 + (lane & 3) * 2 + cb]);

#pragma unroll
        for (int mt = 0; mt < 2; ++mt)
#pragma unroll
            for (int h = 0; h < 2; ++h) {
                int row = wm * 32 + mt * 16 + (lane >> 2) + h * 8;
                float tv = __ldg(&thr[m0 + row]);
#pragma unroll
                for (int j = 0; j < 8; ++j) {
                    float d0 = c2v[j * 2]     - 2.0f * acc[mt][j][h * 2];
                    float d1 = c2v[j * 2 + 1] - 2.0f * acc[mt][j][h * 2 + 1];
                    float dmin = fminf(d0, d1);
                    float o1 = __uint_as_float(
                        __shfl_xor_sync(0xffffffffu, __float_as_uint(dmin), 1));
                    dmin = fminf(dmin, o1);
                    float o2 = __uint_as_float(
                        __shfl_xor_sync(0xffffffffu, __float_as_uint(dmin), 2));
                    dmin = fminf(dmin, o2);
                    float Tg = dmin + tv;
                    unsigned int lm = 0;
                    if (d0 <= Tg) lm |= 1u << ((lane & 3) * 2);
                    if (d1 <= Tg) lm |= 1u << ((lane & 3) * 2 + 1);
                    lm |= __shfl_xor_sync(0xffffffffu, lm, 1);
                    lm |= __shfl_xor_sync(0xffffffffu, lm, 2);
                    if ((lane & 3) == 0)
                        sG[row][wn * 8 + j] = (enc_bits(dmin) & 0xffffff00u) | lm;
                }
            }
        __syncthreads();
        const int gbase = cbk * GRP_CB + ns * 16;
        for (int i = tid; i < 2048; i += 256) {
            int row = i >> 4, j = i & 15;
            gkey[(size_t)(m0 + row) * NGRP + gbase + j] = sG[row][j];
        }
        __syncthreads();
    }

    // inline flag: each warp handles 16 rows; gkey re-read is L2-hot
    for (int rr = 0; rr < 16; ++rr) {
        const int m = m0 + wid * 16 + rr;
        float tv = __ldg(&thr[m]);

        uint32_t kq[8];
        unsigned int mn = ~0u;
#pragma unroll
        for (int q = 0; q < 8; ++q) {
            uint32_t k = gkey[(size_t)m * NGRP + cbk * GRP_CB + q * 32 + lane];
            kq[q] = k;
            unsigned int e = k >> 8;
            if (e < mn) mn = e;
        }
#pragma unroll
        for (int o = 16; o > 0; o >>= 1) {
            unsigned int v = __shfl_xor_sync(0xffffffffu, mn, o);
            if (v < mn) mn = v;
        }
        float M = dec_bits(mn << 8);
        unsigned int encT = enc_bits(M + tv) >> 8;
        unsigned int cbmask = 0;
#pragma unroll
        for (int q = 0; q < 8; ++q)
            if ((kq[q] >> 8) <= encT) cbmask |= 1u << q;

        int cnt = __popc(cbmask);
        int incl = cnt;
#pragma unroll
        for (int o = 1; o < 32; o <<= 1) {
            int v = __shfl_up_sync(0xffffffffu, incl, o);
            if (lane >= o) incl += v;
        }
        int total = __shfl_sync(0xffffffffu, incl, 31);
        unsigned int base = 0;
        if (lane == 31 && total > 0)
            base = atomicAdd(&misc[4 + cbk], (unsigned int)total);
        base = __shfl_sync(0xffffffffu, base, 31);
        int off = (int)base + incl - cnt;
        uint32_t* ip = items + (size_t)cbk * MTOT * GRP_CB;
#pragma unroll
        for (int q = 0; q < 8; ++q)
            if (cbmask & (1u << q)) {
                int g = cbk * GRP_CB + q * 32 + lane;
                ip[off++] = ((unsigned int)m << 18) |
                            ((unsigned int)g << 8) | (kq[q] & 0xffu);
            }
    }
}

// ---------------------------------------------------------------------------
// refine (one codebook): exact fp32 distances for masked codes of each item
// ---------------------------------------------------------------------------
__global__ void refine_kernel(const __nv_bfloat16* __restrict__ Ah,
                              const __nv_bfloat16* __restrict__ Al,
                              const __nv_bfloat16* __restrict__ Bh,
                              const __nv_bfloat16* __restrict__ Bl,
                              const float* __restrict__ c2,
                              const uint32_t* __restrict__ misc,
                              const uint32_t* __restrict__ items,
                              u64* __restrict__ res, int cbk) {
    const int lane = threadIdx.x & 31;
    const int wgid = blockIdx.x * 8 + (threadIdx.x >> 5);
    const int nw = gridDim.x * 8;
    const int cnt = (int)misc[4 + cbk];

    for (int it = wgid; it < cnt; it += nw) {
        unsigned int item = items[it];
        int m = item >> 18;
        int g = (item >> 8) & 1023;
        unsigned int cmask = item & 0xffu;
        int cb = g >> 8;
        int n0 = g * 8;

        float f[16], t0[8], t1[8];
        {
            const uint4* ph = (const uint4*)(Ah + (size_t)m * 512 + lane * 16);
            const uint4* pl = (const uint4*)(Al + (size_t)m * 512 + lane * 16);
            uint4 h0 = ph[0], h1 = ph[1], l0v = pl[0], l1v = pl[1];
            bf8(h0, f); bf8(h1, f + 8);
            bf8(l0v, t0); bf8(l1v, t1);
#pragma unroll
            for (int e = 0; e < 8; ++e)  f[e] += t0[e];
#pragma unroll
            for (int e = 0; e < 8; ++e)  f[e + 8] += t1[e];
        }

        u64 best = ~0ull;
        unsigned int mm = cmask;
        while (mm) {
            int c = __ffs(mm) - 1;
            mm &= mm - 1;
            int n = n0 + c;
            const uint4* pb = (const uint4*)(Bh + (size_t)n * 512 + lane * 16);
            const uint4* pq = (const uint4*)(Bl + (size_t)n * 512 + lane * 16);
            uint4 b0 = pb[0], b1 = pb[1], q0 = pq[0], q1 = pq[1];
            float g0[8], g1[8], r0[8], r1[8];
            bf8(b0, g0); bf8(b1, g1); bf8(q0, r0); bf8(q1, r1);
            float dot = 0.0f;
#pragma unroll
            for (int e = 0; e < 8; ++e) dot = fmaf(f[e], g0[e] + r0[e], dot);
#pragma unroll
            for (int e = 0; e < 8; ++e) dot = fmaf(f[e + 8], g1[e] + r1[e], dot);
#pragma unroll
            for (int o = 16; o > 0; o >>= 1)
                dot += __shfl_down_sync(0xffffffffu, dot, o);
            if (lane == 0) {
                float d = __ldg(&c2[n]) - 2.0f * dot;
                u64 k = dist_key(d, n);
                if (k < best) best = k;
            }
        }
        if (lane == 0 && best != ~0ull) atomicMin(&res[m * 4 + cb], best);
    }
}

// ---------------------------------------------------------------------------
// Finalize: tokens from g_res + embedding mean
// ---------------------------------------------------------------------------
__global__ void finalize_kernel(const u64* __restrict__ res,
                                const float* __restrict__ emb_table,
                                float* __restrict__ out) {
    __shared__ int tok[KCB];
    const int m = blockIdx.x;
    const int b = m >> 12, l = m & 4095;
    const int tid = threadIdx.x;

    if (tid < KCB) {
        int t = ((int)(res[m * 4 + tid] & 0xffffffffu)) & (VOCAB - 1);
        tok[tid] = t;
        out[((size_t)b * KCB + tid) * L3O + l] = (float)t;
    }
    __syncthreads();

    float* out_emb = out + (size_t)NB * KCB * L3O;
    int t0 = tok[0], t1 = tok[1], t2 = tok[2], t3 = tok[3];
    for (int h = tid; h < 512; h += 128) {
        float s = emb_table[(size_t)t0 * 512 + h] + emb_table[(size_t)t1 * 512 + h]
                + emb_table[(size_t)t2 * 512 + h] + emb_table[(size_t)t3 * 512 + h];
        out_emb[((size_t)b * L3O + l) * 512 + h] = 0.25f * s;
    }
}

// ---------------------------------------------------------------------------
extern "C" void kernel_launch(void* const* d_in, const int* in_sizes, int n_in,
                              void* d_out, int out_size) {
    const float* audio = (const float*)d_in[0];
    const float* w1    = (const float*)d_in[1];
    const float* b1    = (const float*)d_in[2];
    const float* w2    = (const float*)d_in[3];
    const float* b2    = (const float*)d_in[4];
    const float* w3    = (const float*)d_in[5];
    const float* b3    = (const float*)d_in[6];
    const float* cb    = (const float*)d_in[7];
    const float* emb   = (const float*)d_in[8];
    float* out = (float*)d_out;

    __nv_bfloat16 *x1h, *x1l, *x2h, *x2l, *w2h, *w2l, *w3h, *w3l;
    __nv_bfloat16 *ah, *al, *bh, *bl;
    float *c2p, *thrp;
    u64 *resp;
    uint32_t *gkeyp, *miscp, *itemsp;
    cudaGetSymbolAddress((void**)&x1h, g_X1h);
    cudaGetSymbolAddress((void**)&x1l, g_X1l);
    cudaGetSymbolAddress((void**)&x2h, g_X2h);
    cudaGetSymbolAddress((void**)&x2l, g_X2l);
    cudaGetSymbolAddress((void**)&w2h, g_W2h);
    cudaGetSymbolAddress((void**)&w2l, g_W2l);
    cudaGetSymbolAddress((void**)&w3h, g_W3h);
    cudaGetSymbolAddress((void**)&w3l, g_W3l);
    cudaGetSymbolAddress((void**)&ah,  g_Ah);
    cudaGetSymbolAddress((void**)&al,  g_Al);
    cudaGetSymbolAddress((void**)&bh,  g_Bh);
    cudaGetSymbolAddress((void**)&bl,  g_Bl);
    cudaGetSymbolAddress((void**)&c2p, g_c2);
    cudaGetSymbolAddress((void**)&thrp, g_thr);
    cudaGetSymbolAddress((void**)&gkeyp, g_gkey32);
    cudaGetSymbolAddress((void**)&itemsp, g_items);
    cudaGetSymbolAddress((void**)&miscp, g_misc);
    cudaGetSymbolAddress((void**)&resp, g_res);

    const size_t ITEMS_CB = (size_t)MTOT * GRP_CB;

    // streams/events created per call (correctness + capture only, not replay)
    cudaStream_t side;
    cudaStreamCreateWithFlags(&side, cudaStreamNonBlocking);
    cudaEvent_t eFork, eW2, eW3, eSB, eA[4], eSideDone;
    cudaEventCreateWithFlags(&eFork, cudaEventDisableTiming);
    cudaEventCreateWithFlags(&eW2,   cudaEventDisableTiming);
    cudaEventCreateWithFlags(&eW3,   cudaEventDisableTiming);
    cudaEventCreateWithFlags(&eSB,   cudaEventDisableTiming);
    for (int i = 0; i < 4; ++i)
        cudaEventCreateWithFlags(&eA[i], cudaEventDisableTiming);
    cudaEventCreateWithFlags(&eSideDone, cudaEventDisableTiming);

    cudaEventRecord(eFork, 0);
    cudaStreamWaitEvent(side, eFork, 0);
    split_W<<<(C2C * C1 * 7 + 255) / 256, 256, 0, side>>>(w2, w2h, w2l, C2C, C1);
    cudaEventRecord(eW2, side);
    split_W<<<(C3 * C2C * 7 + 255) / 256, 256, 0, side>>>(w3, w3h, w3l, C3, C2C);
    cudaEventRecord(eW3, side);
    splitb_kernel<<<NCODES / 8, 256, 0, side>>>(cb, bh, bl, c2p, miscp);
    cudaEventRecord(eSB, side);

    // main stream: audio chain
    prep_kernel<<<(MTOT * KCB + 255) / 256, 256>>>(
        resp, miscp, (uint32_t*)x1h, (uint32_t*)x1l, (uint32_t*)x2h, (uint32_t*)x2l);
    conv1_kernel<<<dim3(L1O / 2, 1, NB), 256>>>(audio, w1, b1, x1h, x1l);

    cudaStreamWaitEvent(0, eW2, 0);
    cudaFuncSetAttribute(conv_mma<C1>, cudaFuncAttributeMaxDynamicSharedMemorySize,
                         CBUF);
    conv_mma<C1><<<dim3(L2O / 128, C2C / 128, NB), 256, CBUF>>>(
        x1h, x1l, w2h, w2l, b2, x2h, x2l, L1O, L2O, C2C, 1, 8, 4);

    cudaStreamWaitEvent(0, eW3, 0);
    cudaFuncSetAttribute(conv_mma<C2C>, cudaFuncAttributeMaxDynamicSharedMemorySize,
                         CBUF);
    conv_mma<C2C><<<dim3(L3O / 128, C3 / 128, NB), 256, CBUF>>>(
        x2h, x2l, w3h, w3l, b3, ah, al, L2O, L3O, C3, 0, 0, 0);

    cudaStreamWaitEvent(0, eSB, 0);
    thr_kernel<<<MTOT / 8, 256>>>(ah, al, miscp, thrp);

    // per-codebook fused approx+flag (main) with refine pipelined on side
    cudaFuncSetAttribute(vq_fused, cudaFuncAttributeMaxDynamicSharedMemorySize,
                         VSMEM);
    for (int cbk = 0; cbk < 4; ++cbk) {
        vq_fused<<<MTOT / 128, 256, VSMEM>>>(
            ah, bh, c2p, thrp, gkeyp, miscp, itemsp, cbk);
        cudaEventRecord(eA[cbk], 0);
        cudaStreamWaitEvent(side, eA[cbk], 0);
        refine_kernel<<<512, 256, 0, side>>>(
            ah, al, bh, bl, c2p, miscp, itemsp + cbk * ITEMS_CB, resp, cbk);
    }
    cudaEventRecord(eSideDone, side);
    cudaStreamWaitEvent(0, eSideDone, 0);

    finalize_kernel<<<MTOT, 128>>>(resp, emb, out);
}